// round 1
// baseline (speedup 1.0000x reference)
#include <cuda_runtime.h>
#include <cuda_bf16.h>
#include <math.h>

// ---------------- problem constants ----------------
#define T_TOK   4096
#define STATE_D 1024
#define EMBED_D 512
#define DIST_D  20
#define HID     1024
#define GI_D    2580      // 2*STATE_D + EMBED_D + DIST_D
#define MAX_W   10

// ---------------- scratch (static device globals; no allocs) --------------
__device__ float g_h1[(size_t)T_TOK * HID];
__device__ float g_h2[(size_t)T_TOK * HID];
__device__ float g_attns[T_TOK];
__device__ float g_s1[(size_t)40960 * HID];
__device__ float g_s2[(size_t)40960 * HID];

// ---------------- SGEMM: C[M,N] = act(A[M,K] @ B[K,N] + bias) --------------
// A row-major with leading dim lda, B row-major [K,N], N % 128 == 0.
// 128x128 block tile, BK=8, 256 threads, 8x8 per thread.
template <bool RELU>
__global__ __launch_bounds__(256)
void sgemm_kernel(const float* __restrict__ A, const float* __restrict__ B,
                  const float* __restrict__ bias, float* __restrict__ C,
                  int M, int N, int K, int lda)
{
    __shared__ float As[8][128];
    __shared__ float Bs[8][128];

    const int tid = threadIdx.x;
    const int bm = blockIdx.y * 128;
    const int bn = blockIdx.x * 128;
    const int tx = tid & 15;      // 0..15 -> n
    const int ty = tid >> 4;      // 0..15 -> m

    const int arow = tid >> 1;          // 0..127
    const int acol = (tid & 1) * 4;     // 0 or 4
    const int brow = tid >> 5;          // 0..7
    const int bcol = (tid & 31) * 4;    // 0..124

    float acc[8][8];
#pragma unroll
    for (int i = 0; i < 8; i++)
#pragma unroll
        for (int j = 0; j < 8; j++) acc[i][j] = 0.f;

    for (int k0 = 0; k0 < K; k0 += 8) {
        // --- load A tile (128 x 8), transposed into As[k][m] ---
        {
            const int gr = bm + arow;
            float4 av = make_float4(0.f, 0.f, 0.f, 0.f);
            if (gr < M) {
                const int gk = k0 + acol;
                if (gk + 3 < K) {
                    av = *reinterpret_cast<const float4*>(A + (size_t)gr * lda + gk);
                } else {
                    float t[4] = {0.f, 0.f, 0.f, 0.f};
#pragma unroll
                    for (int q = 0; q < 4; q++)
                        if (gk + q < K) t[q] = A[(size_t)gr * lda + gk + q];
                    av = make_float4(t[0], t[1], t[2], t[3]);
                }
            }
            As[acol + 0][arow] = av.x;
            As[acol + 1][arow] = av.y;
            As[acol + 2][arow] = av.z;
            As[acol + 3][arow] = av.w;
        }
        // --- load B tile (8 x 128) ---
        {
            const int gk = k0 + brow;
            float4 bv = make_float4(0.f, 0.f, 0.f, 0.f);
            if (gk < K)
                bv = *reinterpret_cast<const float4*>(B + (size_t)gk * N + bn + bcol);
            *reinterpret_cast<float4*>(&Bs[brow][bcol]) = bv;
        }
        __syncthreads();

#pragma unroll
        for (int k = 0; k < 8; k++) {
            float a[8], b[8];
            *reinterpret_cast<float4*>(a)     = *reinterpret_cast<const float4*>(&As[k][ty * 8]);
            *reinterpret_cast<float4*>(a + 4) = *reinterpret_cast<const float4*>(&As[k][ty * 8 + 4]);
            *reinterpret_cast<float4*>(b)     = *reinterpret_cast<const float4*>(&Bs[k][tx * 8]);
            *reinterpret_cast<float4*>(b + 4) = *reinterpret_cast<const float4*>(&Bs[k][tx * 8 + 4]);
#pragma unroll
            for (int i = 0; i < 8; i++)
#pragma unroll
                for (int j = 0; j < 8; j++)
                    acc[i][j] += a[i] * b[j];
        }
        __syncthreads();
    }

    // --- epilogue: bias + (relu) ---
    const int ncol = bn + tx * 8;
    float bv[8];
#pragma unroll
    for (int j = 0; j < 8; j++) bv[j] = bias[ncol + j];

#pragma unroll
    for (int i = 0; i < 8; i++) {
        const int r = bm + ty * 8 + i;
        if (r < M) {
            float v[8];
#pragma unroll
            for (int j = 0; j < 8; j++) {
                float x = acc[i][j] + bv[j];
                if (RELU) x = fmaxf(x, 0.f);
                v[j] = x;
            }
            *reinterpret_cast<float4*>(C + (size_t)r * N + ncol)     = *reinterpret_cast<float4*>(v);
            *reinterpret_cast<float4*>(C + (size_t)r * N + ncol + 4) = *reinterpret_cast<float4*>(v + 4);
        }
    }
}

// ---------------- GEMV: y[m] = dot(X[m,:K], w) + b0 ----------------
__global__ void gemv_kernel(const float* __restrict__ X, const float* __restrict__ w,
                            const float* __restrict__ b, float* __restrict__ y,
                            int M, int K)
{
    const int row  = blockIdx.x * (blockDim.x >> 5) + (threadIdx.x >> 5);
    const int lane = threadIdx.x & 31;
    if (row >= M) return;
    const float4* x4 = reinterpret_cast<const float4*>(X + (size_t)row * K);
    const float4* w4 = reinterpret_cast<const float4*>(w);
    float acc = 0.f;
    const int K4 = K >> 2;
    for (int i = lane; i < K4; i += 32) {
        float4 a = x4[i], c = w4[i];
        acc += a.x * c.x + a.y * c.y + a.z * c.z + a.w * c.w;
    }
#pragma unroll
    for (int o = 16; o; o >>= 1) acc += __shfl_xor_sync(0xffffffffu, acc, o);
    if (lane == 0) y[row] = acc + b[0];
}

// ---------------- span featurization: builds g_i[N, 2580] ----------------
// one warp per span
__global__ void span_kernel(const float* __restrict__ states, const float* __restrict__ embeds,
                            const float* __restrict__ wemb, const int* __restrict__ starts,
                            const int* __restrict__ widths, const float* __restrict__ attns,
                            float* __restrict__ gi, int N)
{
    const int warp = (blockIdx.x * blockDim.x + threadIdx.x) >> 5;
    const int lane = threadIdx.x & 31;
    if (warp >= N) return;

    const int s = starts[warp];
    const int w = widths[warp];

    // --- softmax over the w valid slots (lane j holds slot j) ---
    float a = (lane < w) ? attns[s + lane] : -INFINITY;
    float m = a;
#pragma unroll
    for (int o = 16; o; o >>= 1) m = fmaxf(m, __shfl_xor_sync(0xffffffffu, m, o));
    float e = (lane < w) ? expf(a - m) : 0.f;
    float sum = e;
#pragma unroll
    for (int o = 16; o; o >>= 1) sum += __shfl_xor_sync(0xffffffffu, sum, o);
    const float wgt = e / sum;

    float* out = gi + (size_t)warp * GI_D;

    // --- start / end state copies (each 1024 floats = 256 float4) ---
    const float4* ss = reinterpret_cast<const float4*>(states + (size_t)s * STATE_D);
    const float4* se = reinterpret_cast<const float4*>(states + (size_t)(s + w - 1) * STATE_D);
    float4* o0 = reinterpret_cast<float4*>(out);
    float4* o1 = reinterpret_cast<float4*>(out + STATE_D);
#pragma unroll
    for (int i = lane; i < STATE_D / 4; i += 32) {
        o0[i] = ss[i];
        o1[i] = se[i];
    }

    // --- attention-pooled embeds (512 floats = 128 float4) ---
    float4* o2 = reinterpret_cast<float4*>(out + 2 * STATE_D);
#pragma unroll
    for (int i = lane; i < EMBED_D / 4; i += 32) {
        float4 acc = make_float4(0.f, 0.f, 0.f, 0.f);
        for (int j = 0; j < w; j++) {
            const float wj = __shfl_sync(0xffffffffu, wgt, j);
            const float4 ev = reinterpret_cast<const float4*>(embeds + (size_t)(s + j) * EMBED_D)[i];
            acc.x += wj * ev.x; acc.y += wj * ev.y;
            acc.z += wj * ev.z; acc.w += wj * ev.w;
        }
        o2[i] = acc;
    }

    // --- width bucket embedding (bins 1,2,3,4,8,16,32,64; w <= 10) ---
    const int bucket = (w >= 1) + (w >= 2) + (w >= 3) + (w >= 4) + (w >= 8);
    if (lane < DIST_D)
        out[2 * STATE_D + EMBED_D + lane] = wemb[bucket * DIST_D + lane];
}

// ---------------- launch ----------------
extern "C" void kernel_launch(void* const* d_in, const int* in_sizes, int n_in,
                              void* d_out, int out_size)
{
    const float* states = (const float*)d_in[0];
    const float* embeds = (const float*)d_in[1];
    const float* aW1 = (const float*)d_in[2];  const float* ab1 = (const float*)d_in[3];
    const float* aW2 = (const float*)d_in[4];  const float* ab2 = (const float*)d_in[5];
    const float* aW3 = (const float*)d_in[6];  const float* ab3 = (const float*)d_in[7];
    const float* sW1 = (const float*)d_in[8];  const float* sb1 = (const float*)d_in[9];
    const float* sW2 = (const float*)d_in[10]; const float* sb2 = (const float*)d_in[11];
    const float* sW3 = (const float*)d_in[12]; const float* sb3 = (const float*)d_in[13];
    const float* wemb = (const float*)d_in[14];
    const int* sstarts = (const int*)d_in[15];
    const int* swidths = (const int*)d_in[16];
    const int N = in_sizes[15];   // 40915 spans

    float* out    = (float*)d_out;
    float* gi     = out;                         // [N, 2580]
    float* scores = out + (size_t)N * GI_D;      // [N]

    float *h1, *h2, *attns, *s1, *s2;
    cudaGetSymbolAddress((void**)&h1,    g_h1);
    cudaGetSymbolAddress((void**)&h2,    g_h2);
    cudaGetSymbolAddress((void**)&attns, g_attns);
    cudaGetSymbolAddress((void**)&s1,    g_s1);
    cudaGetSymbolAddress((void**)&s2,    g_s2);

    // 1) attention MLP over tokens
    {
        dim3 grid(HID / 128, T_TOK / 128);
        sgemm_kernel<true><<<grid, 256>>>(states, aW1, ab1, h1, T_TOK, HID, STATE_D, STATE_D);
        sgemm_kernel<true><<<grid, 256>>>(h1, aW2, ab2, h2, T_TOK, HID, HID, HID);
        gemv_kernel<<<(T_TOK * 32 + 255) / 256, 256>>>(h2, aW3, ab3, attns, T_TOK, HID);
    }

    // 2) span featurization -> g_i (directly into d_out)
    {
        const int warps_per_block = 8;
        const int blocks = (N + warps_per_block - 1) / warps_per_block;
        span_kernel<<<blocks, warps_per_block * 32>>>(states, embeds, wemb, sstarts, swidths,
                                                      attns, gi, N);
    }

    // 3) score MLP over spans
    {
        dim3 grid(HID / 128, (N + 127) / 128);
        sgemm_kernel<true><<<grid, 256>>>(gi, sW1, sb1, s1, N, HID, GI_D, GI_D);
        sgemm_kernel<true><<<grid, 256>>>(s1, sW2, sb2, s2, N, HID, HID, HID);
        gemv_kernel<<<(N * 32 + 255) / 256, 256>>>(s2, sW3, sb3, scores, N, HID);
    }
}

// round 2
// speedup vs baseline: 2.6818x; 2.6818x over previous
#include <cuda_runtime.h>
#include <cuda_bf16.h>
#include <math.h>
#include <stdint.h>

// ---------------- problem constants ----------------
#define T_TOK   4096
#define STATE_D 1024
#define EMBED_D 512
#define DIST_D  20
#define HID     1024
#define GI_D    2580      // 2*STATE_D + EMBED_D + DIST_D
#define MAX_W   10

// ---------------- scratch (static device globals; no allocs) --------------
__device__ float g_h1[(size_t)T_TOK * HID];
__device__ float g_h2[(size_t)T_TOK * HID];
__device__ float g_attns[T_TOK];
__device__ float g_s1[(size_t)40960 * HID];
__device__ float g_s2[(size_t)40960 * HID];

// ===================== fp32 SIMT SGEMM (attn path only) ====================
template <bool RELU>
__global__ __launch_bounds__(256)
void sgemm_kernel(const float* __restrict__ A, const float* __restrict__ B,
                  const float* __restrict__ bias, float* __restrict__ C,
                  int M, int N, int K, int lda)
{
    __shared__ float As[8][128];
    __shared__ float Bs[8][128];

    const int tid = threadIdx.x;
    const int bm = blockIdx.y * 128;
    const int bn = blockIdx.x * 128;
    const int tx = tid & 15;
    const int ty = tid >> 4;

    const int arow = tid >> 1;
    const int acol = (tid & 1) * 4;
    const int brow = tid >> 5;
    const int bcol = (tid & 31) * 4;

    float acc[8][8];
#pragma unroll
    for (int i = 0; i < 8; i++)
#pragma unroll
        for (int j = 0; j < 8; j++) acc[i][j] = 0.f;

    for (int k0 = 0; k0 < K; k0 += 8) {
        {
            const int gr = bm + arow;
            float4 av = make_float4(0.f, 0.f, 0.f, 0.f);
            if (gr < M) {
                const int gk = k0 + acol;
                if (gk + 3 < K) {
                    av = *reinterpret_cast<const float4*>(A + (size_t)gr * lda + gk);
                } else {
                    float t[4] = {0.f, 0.f, 0.f, 0.f};
#pragma unroll
                    for (int q = 0; q < 4; q++)
                        if (gk + q < K) t[q] = A[(size_t)gr * lda + gk + q];
                    av = make_float4(t[0], t[1], t[2], t[3]);
                }
            }
            As[acol + 0][arow] = av.x;
            As[acol + 1][arow] = av.y;
            As[acol + 2][arow] = av.z;
            As[acol + 3][arow] = av.w;
        }
        {
            const int gk = k0 + brow;
            float4 bv = make_float4(0.f, 0.f, 0.f, 0.f);
            if (gk < K)
                bv = *reinterpret_cast<const float4*>(B + (size_t)gk * N + bn + bcol);
            *reinterpret_cast<float4*>(&Bs[brow][bcol]) = bv;
        }
        __syncthreads();

#pragma unroll
        for (int k = 0; k < 8; k++) {
            float a[8], b[8];
            *reinterpret_cast<float4*>(a)     = *reinterpret_cast<const float4*>(&As[k][ty * 8]);
            *reinterpret_cast<float4*>(a + 4) = *reinterpret_cast<const float4*>(&As[k][ty * 8 + 4]);
            *reinterpret_cast<float4*>(b)     = *reinterpret_cast<const float4*>(&Bs[k][tx * 8]);
            *reinterpret_cast<float4*>(b + 4) = *reinterpret_cast<const float4*>(&Bs[k][tx * 8 + 4]);
#pragma unroll
            for (int i = 0; i < 8; i++)
#pragma unroll
                for (int j = 0; j < 8; j++)
                    acc[i][j] += a[i] * b[j];
        }
        __syncthreads();
    }

    const int ncol = bn + tx * 8;
    float bv[8];
#pragma unroll
    for (int j = 0; j < 8; j++) bv[j] = bias[ncol + j];

#pragma unroll
    for (int i = 0; i < 8; i++) {
        const int r = bm + ty * 8 + i;
        if (r < M) {
            float v[8];
#pragma unroll
            for (int j = 0; j < 8; j++) {
                float x = acc[i][j] + bv[j];
                if (RELU) x = fmaxf(x, 0.f);
                v[j] = x;
            }
            *reinterpret_cast<float4*>(C + (size_t)r * N + ncol)     = *reinterpret_cast<float4*>(v);
            *reinterpret_cast<float4*>(C + (size_t)r * N + ncol + 4) = *reinterpret_cast<float4*>(v + 4);
        }
    }
}

// ===================== tf32 tensor-core GEMM (score path) ==================
// C[M,N] = relu(A[M,K] @ B[K,N] + bias), N % 128 == 0.
// 128x128x16 tile, 256 threads, 2x4 warps (64x32 warp tile), m16n8k8 tf32 mma,
// double-buffered SMEM. Bank-conflict-free fragment loads:
//   As m-major, stride 20 (20 % 32 == 20 -> lanes hit 32 distinct banks)
//   Bs k-major, stride 136 (row offset 8 banks -> distinct banks)
__device__ __forceinline__ uint32_t f2tf32(float x) {
    uint32_t r;
    asm("cvt.rna.tf32.f32 %0, %1;" : "=r"(r) : "f"(x));
    return r;
}

template <bool RELU>
__global__ __launch_bounds__(256)
void tf32_gemm_kernel(const float* __restrict__ A, const float* __restrict__ B,
                      const float* __restrict__ bias, float* __restrict__ C,
                      int M, int N, int K, int lda)
{
    constexpr int BM = 128, BN = 128, BK = 16;
    constexpr int ASTR = BK + 4;    // 20
    constexpr int BSTR = BN + 8;    // 136

    __shared__ uint32_t As[2][BM * ASTR];
    __shared__ uint32_t Bs[2][BK * BSTR];

    const int tid  = threadIdx.x;
    const int bm   = blockIdx.y * BM;
    const int bn   = blockIdx.x * BN;
    const int warp = tid >> 5;
    const int lane = tid & 31;
    const int g    = lane >> 2;     // 0..7
    const int tig  = lane & 3;      // 0..3
    const int wm   = (warp & 1) * 64;
    const int wn   = (warp >> 1) * 32;

    // global-load assignments
    const int arow = tid >> 1;            // 0..127
    const int acol = (tid & 1) * 8;       // 0 or 8
    const int brow = tid >> 4;            // 0..15
    const int bcol = (tid & 15) * 8;      // 0..120

    float acc[4][4][4];
#pragma unroll
    for (int mf = 0; mf < 4; mf++)
#pragma unroll
        for (int nf = 0; nf < 4; nf++)
#pragma unroll
            for (int q = 0; q < 4; q++) acc[mf][nf][q] = 0.f;

    float areg[8], breg[8];

    auto ldgA = [&](int k0) {
        const bool rok = (bm + arow) < M;
        const float* ap = A + (size_t)(bm + arow) * lda + k0 + acol;
        if (rok && (k0 + acol + 7) < K) {
            float4 v0 = *reinterpret_cast<const float4*>(ap);
            float4 v1 = *reinterpret_cast<const float4*>(ap + 4);
            areg[0] = v0.x; areg[1] = v0.y; areg[2] = v0.z; areg[3] = v0.w;
            areg[4] = v1.x; areg[5] = v1.y; areg[6] = v1.z; areg[7] = v1.w;
        } else {
#pragma unroll
            for (int q = 0; q < 8; q++)
                areg[q] = (rok && (k0 + acol + q) < K) ? ap[q] : 0.f;
        }
    };
    auto ldgB = [&](int k0) {
        const int k = k0 + brow;
        if (k < K) {
            const float* bp = B + (size_t)k * N + bn + bcol;
            float4 v0 = *reinterpret_cast<const float4*>(bp);
            float4 v1 = *reinterpret_cast<const float4*>(bp + 4);
            breg[0] = v0.x; breg[1] = v0.y; breg[2] = v0.z; breg[3] = v0.w;
            breg[4] = v1.x; breg[5] = v1.y; breg[6] = v1.z; breg[7] = v1.w;
        } else {
#pragma unroll
            for (int q = 0; q < 8; q++) breg[q] = 0.f;
        }
    };
    auto sts = [&](int buf) {
        uint32_t* ad = &As[buf][arow * ASTR + acol];
#pragma unroll
        for (int q = 0; q < 8; q++) ad[q] = f2tf32(areg[q]);
        uint32_t* bd = &Bs[buf][brow * BSTR + bcol];
#pragma unroll
        for (int q = 0; q < 8; q++) bd[q] = f2tf32(breg[q]);
    };
    auto compute = [&](int buf) {
#pragma unroll
        for (int kk = 0; kk < BK; kk += 8) {
            uint32_t a[4][4], b[4][2];
#pragma unroll
            for (int mf = 0; mf < 4; mf++) {
                const uint32_t* ap = &As[buf][(wm + mf * 16 + g) * ASTR + kk + tig];
                a[mf][0] = ap[0];
                a[mf][1] = ap[8 * ASTR];
                a[mf][2] = ap[4];
                a[mf][3] = ap[8 * ASTR + 4];
            }
#pragma unroll
            for (int nf = 0; nf < 4; nf++) {
                const uint32_t* bp = &Bs[buf][(kk + tig) * BSTR + wn + nf * 8 + g];
                b[nf][0] = bp[0];
                b[nf][1] = bp[4 * BSTR];
            }
#pragma unroll
            for (int mf = 0; mf < 4; mf++)
#pragma unroll
                for (int nf = 0; nf < 4; nf++) {
                    asm volatile(
                        "mma.sync.aligned.m16n8k8.row.col.f32.tf32.tf32.f32 "
                        "{%0,%1,%2,%3}, {%4,%5,%6,%7}, {%8,%9}, {%0,%1,%2,%3};"
                        : "+f"(acc[mf][nf][0]), "+f"(acc[mf][nf][1]),
                          "+f"(acc[mf][nf][2]), "+f"(acc[mf][nf][3])
                        : "r"(a[mf][0]), "r"(a[mf][1]), "r"(a[mf][2]), "r"(a[mf][3]),
                          "r"(b[nf][0]), "r"(b[nf][1]));
                }
        }
    };

    // prologue
    ldgA(0); ldgB(0);
    sts(0);
    __syncthreads();

    int buf = 0;
    for (int k0 = 0; k0 < K; k0 += BK) {
        const bool more = (k0 + BK) < K;
        if (more) { ldgA(k0 + BK); ldgB(k0 + BK); }
        compute(buf);
        if (more) {
            sts(buf ^ 1);
            __syncthreads();
            buf ^= 1;
        }
    }

    // epilogue
#pragma unroll
    for (int nf = 0; nf < 4; nf++) {
        const int col = bn + wn + nf * 8 + 2 * tig;
        const float b0 = bias[col];
        const float b1 = bias[col + 1];
#pragma unroll
        for (int mf = 0; mf < 4; mf++) {
            const int r0 = bm + wm + mf * 16 + g;
            const int r1 = r0 + 8;
            float v0 = acc[mf][nf][0] + b0;
            float v1 = acc[mf][nf][1] + b1;
            float v2 = acc[mf][nf][2] + b0;
            float v3 = acc[mf][nf][3] + b1;
            if (RELU) {
                v0 = fmaxf(v0, 0.f); v1 = fmaxf(v1, 0.f);
                v2 = fmaxf(v2, 0.f); v3 = fmaxf(v3, 0.f);
            }
            if (r0 < M) *reinterpret_cast<float2*>(C + (size_t)r0 * N + col) = make_float2(v0, v1);
            if (r1 < M) *reinterpret_cast<float2*>(C + (size_t)r1 * N + col) = make_float2(v2, v3);
        }
    }
}

// ---------------- GEMV: y[m] = dot(X[m,:K], w) + b0 ----------------
__global__ void gemv_kernel(const float* __restrict__ X, const float* __restrict__ w,
                            const float* __restrict__ b, float* __restrict__ y,
                            int M, int K)
{
    const int row  = blockIdx.x * (blockDim.x >> 5) + (threadIdx.x >> 5);
    const int lane = threadIdx.x & 31;
    if (row >= M) return;
    const float4* x4 = reinterpret_cast<const float4*>(X + (size_t)row * K);
    const float4* w4 = reinterpret_cast<const float4*>(w);
    float acc = 0.f;
    const int K4 = K >> 2;
    for (int i = lane; i < K4; i += 32) {
        float4 a = x4[i], c = w4[i];
        acc += a.x * c.x + a.y * c.y + a.z * c.z + a.w * c.w;
    }
#pragma unroll
    for (int o = 16; o; o >>= 1) acc += __shfl_xor_sync(0xffffffffu, acc, o);
    if (lane == 0) y[row] = acc + b[0];
}

// ---------------- span featurization: builds g_i[N, 2580] ----------------
__global__ void span_kernel(const float* __restrict__ states, const float* __restrict__ embeds,
                            const float* __restrict__ wemb, const int* __restrict__ starts,
                            const int* __restrict__ widths, const float* __restrict__ attns,
                            float* __restrict__ gi, int N)
{
    const int warp = (blockIdx.x * blockDim.x + threadIdx.x) >> 5;
    const int lane = threadIdx.x & 31;
    if (warp >= N) return;

    const int s = starts[warp];
    const int w = widths[warp];

    float a = (lane < w) ? attns[s + lane] : -INFINITY;
    float m = a;
#pragma unroll
    for (int o = 16; o; o >>= 1) m = fmaxf(m, __shfl_xor_sync(0xffffffffu, m, o));
    float e = (lane < w) ? expf(a - m) : 0.f;
    float sum = e;
#pragma unroll
    for (int o = 16; o; o >>= 1) sum += __shfl_xor_sync(0xffffffffu, sum, o);
    const float wgt = e / sum;

    float* out = gi + (size_t)warp * GI_D;

    const float4* ss = reinterpret_cast<const float4*>(states + (size_t)s * STATE_D);
    const float4* se = reinterpret_cast<const float4*>(states + (size_t)(s + w - 1) * STATE_D);
    float4* o0 = reinterpret_cast<float4*>(out);
    float4* o1 = reinterpret_cast<float4*>(out + STATE_D);
#pragma unroll
    for (int i = lane; i < STATE_D / 4; i += 32) {
        o0[i] = ss[i];
        o1[i] = se[i];
    }

    float4* o2 = reinterpret_cast<float4*>(out + 2 * STATE_D);
#pragma unroll
    for (int i = lane; i < EMBED_D / 4; i += 32) {
        float4 acc = make_float4(0.f, 0.f, 0.f, 0.f);
        for (int j = 0; j < w; j++) {
            const float wj = __shfl_sync(0xffffffffu, wgt, j);
            const float4 ev = reinterpret_cast<const float4*>(embeds + (size_t)(s + j) * EMBED_D)[i];
            acc.x += wj * ev.x; acc.y += wj * ev.y;
            acc.z += wj * ev.z; acc.w += wj * ev.w;
        }
        o2[i] = acc;
    }

    const int bucket = (w >= 1) + (w >= 2) + (w >= 3) + (w >= 4) + (w >= 8);
    if (lane < DIST_D)
        out[2 * STATE_D + EMBED_D + lane] = wemb[bucket * DIST_D + lane];
}

// ---------------- launch ----------------
extern "C" void kernel_launch(void* const* d_in, const int* in_sizes, int n_in,
                              void* d_out, int out_size)
{
    const float* states = (const float*)d_in[0];
    const float* embeds = (const float*)d_in[1];
    const float* aW1 = (const float*)d_in[2];  const float* ab1 = (const float*)d_in[3];
    const float* aW2 = (const float*)d_in[4];  const float* ab2 = (const float*)d_in[5];
    const float* aW3 = (const float*)d_in[6];  const float* ab3 = (const float*)d_in[7];
    const float* sW1 = (const float*)d_in[8];  const float* sb1 = (const float*)d_in[9];
    const float* sW2 = (const float*)d_in[10]; const float* sb2 = (const float*)d_in[11];
    const float* sW3 = (const float*)d_in[12]; const float* sb3 = (const float*)d_in[13];
    const float* wemb = (const float*)d_in[14];
    const int* sstarts = (const int*)d_in[15];
    const int* swidths = (const int*)d_in[16];
    const int N = in_sizes[15];   // 40915 spans

    float* out    = (float*)d_out;
    float* gi     = out;                         // [N, 2580]
    float* scores = out + (size_t)N * GI_D;      // [N]

    float *h1, *h2, *attns, *s1, *s2;
    cudaGetSymbolAddress((void**)&h1,    g_h1);
    cudaGetSymbolAddress((void**)&h2,    g_h2);
    cudaGetSymbolAddress((void**)&attns, g_attns);
    cudaGetSymbolAddress((void**)&s1,    g_s1);
    cudaGetSymbolAddress((void**)&s2,    g_s2);

    // 1) attention MLP over tokens (fp32 — feeds g_i, keep exact)
    {
        dim3 grid(HID / 128, T_TOK / 128);
        sgemm_kernel<true><<<grid, 256>>>(states, aW1, ab1, h1, T_TOK, HID, STATE_D, STATE_D);
        sgemm_kernel<true><<<grid, 256>>>(h1, aW2, ab2, h2, T_TOK, HID, HID, HID);
        gemv_kernel<<<(T_TOK * 32 + 255) / 256, 256>>>(h2, aW3, ab3, attns, T_TOK, HID);
    }

    // 2) span featurization -> g_i (directly into d_out)
    {
        const int warps_per_block = 8;
        const int blocks = (N + warps_per_block - 1) / warps_per_block;
        span_kernel<<<blocks, warps_per_block * 32>>>(states, embeds, wemb, sstarts, swidths,
                                                      attns, gi, N);
    }

    // 3) score MLP over spans (tf32 tensor cores — only affects scores)
    {
        dim3 grid(HID / 128, (N + 127) / 128);
        tf32_gemm_kernel<true><<<grid, 256>>>(gi, sW1, sb1, s1, N, HID, GI_D, GI_D);
        tf32_gemm_kernel<true><<<grid, 256>>>(s1, sW2, sb2, s2, N, HID, HID, HID);
        gemv_kernel<<<(N * 32 + 255) / 256, 256>>>(s2, sW3, sb3, scores, N, HID);
    }
}

// round 5
// speedup vs baseline: 2.9589x; 1.1033x over previous
#include <cuda_runtime.h>
#include <cuda_bf16.h>
#include <math.h>
#include <stdint.h>

// ---------------- problem constants ----------------
#define T_TOK   4096
#define STATE_D 1024
#define EMBED_D 512
#define DIST_D  20
#define HID     1024
#define GI_D    2580      // 2*STATE_D + EMBED_D + DIST_D
#define MAX_W   10

// ---------------- scratch (static device globals; no allocs) --------------
__device__ float g_h1[(size_t)T_TOK * HID];
__device__ float g_h2[(size_t)T_TOK * HID];
__device__ float g_attns[T_TOK];
__device__ float g_s1[(size_t)40960 * HID];
__device__ float g_s2[(size_t)40960 * HID];

__device__ __forceinline__ uint32_t f2tf32(float x) {
    uint32_t r;
    asm("cvt.rna.tf32.f32 %0, %1;" : "=r"(r) : "f"(x));
    return r;
}

// ============= tf32 mma.sync GEMM, fragment-permuted SMEM ==================
// C[M,N] = relu(A[M,K] @ B[K,N] + bias), N % 256 == 0.
// Block tile 128x256x16, 8 warps in 2(m) x 4(n), warp tile 64x64,
// m16n8k8 tf32 mma. SMEM pre-permuted to fragment layout:
//   A: [2 bufs][16 groups (kc*8+fr)][32 lanes][4 slots]  -> LDS.128 per frag
//   B: [2 bufs][64 groups (kc*32+nf), stride 66][32 lanes x 2 slots] -> LDS.64
#define TFG_AS_BUF 2048            // u32 per A buffer
#define TFG_BS_BUF 4224            // u32 per B buffer (64 groups * 66)
#define TFG_SMEM_BYTES ((2 * TFG_AS_BUF + 2 * TFG_BS_BUF) * 4)   // 50176

template <bool RELU>
__global__ __launch_bounds__(256, 1)
void tf32_gemm_kernel(const float* __restrict__ A, const float* __restrict__ B,
                      const float* __restrict__ bias, float* __restrict__ C,
                      int M, int N, int K, int lda)
{
    extern __shared__ uint32_t sh[];
    uint32_t* As = sh;                       // 2 * 2048
    uint32_t* Bs = sh + 2 * TFG_AS_BUF;      // 2 * 4224

    const int tid  = threadIdx.x;
    const int warp = tid >> 5;
    const int lane = tid & 31;
    const int g    = lane >> 2;
    const int tig  = lane & 3;
    const int bm   = blockIdx.y * 128;
    const int n0   = blockIdx.x * 256;
    const int wm   = (warp & 1) * 64;        // warp row offset
    const int wn   = (warp >> 1) * 64;       // warp col offset
    const int wmg  = wm >> 4;                // fr offset
    const int wng  = wn >> 3;                // nf offset

    float acc[4][8][4];
#pragma unroll
    for (int mf = 0; mf < 4; mf++)
#pragma unroll
        for (int nf = 0; nf < 8; nf++)
#pragma unroll
            for (int q = 0; q < 4; q++) acc[mf][nf][q] = 0.f;

    float  a_st[2][4];
    float4 b_st[4];

    auto ldgA = [&](int k0) {
#pragma unroll
        for (int j = 0; j < 2; j++) {
            const int slot = tid + j * 256;        // 0..511
            const int grp  = slot >> 5;            // kc*8 + fr
            const int ln   = slot & 31;
            const int kc   = grp >> 3, fr = grp & 7;
            const int gg   = ln >> 2,  tt = ln & 3;
            const int r0   = bm + fr * 16 + gg;
            const int c0   = k0 + kc * 8 + tt;
            const float* base = A + (size_t)r0 * lda + c0;
            const bool rok0 = r0 < M, rok1 = (r0 + 8) < M;
            const bool cok0 = c0 < K, cok1 = (c0 + 4) < K;
            a_st[j][0] = (rok0 && cok0) ? base[0] : 0.f;
            a_st[j][1] = (rok1 && cok0) ? base[(size_t)8 * lda] : 0.f;
            a_st[j][2] = (rok0 && cok1) ? base[4] : 0.f;
            a_st[j][3] = (rok1 && cok1) ? base[(size_t)8 * lda + 4] : 0.f;
        }
    };
    auto stsA = [&](int buf) {
#pragma unroll
        for (int j = 0; j < 2; j++) {
            const int slot = tid + j * 256;
            uint4 u;
            u.x = f2tf32(a_st[j][0]); u.y = f2tf32(a_st[j][1]);
            u.z = f2tf32(a_st[j][2]); u.w = f2tf32(a_st[j][3]);
            *reinterpret_cast<uint4*>(As + buf * TFG_AS_BUF + slot * 4) = u;
        }
    };
    auto ldgB = [&](int k0) {
#pragma unroll
        for (int j = 0; j < 4; j++) {
            const int i  = tid + j * 256;          // 0..1023
            const int k  = i >> 6;                 // 0..15
            const int n4 = i & 63;
            const int gk = k0 + k;
            if (gk < K)
                b_st[j] = *reinterpret_cast<const float4*>(B + (size_t)gk * N + n0 + n4 * 4);
            else
                b_st[j] = make_float4(0.f, 0.f, 0.f, 0.f);
        }
    };
    auto stsB = [&](int buf) {
#pragma unroll
        for (int j = 0; j < 4; j++) {
            const int i  = tid + j * 256;
            const int k  = i >> 6, n4 = i & 63;
            const int kc = k >> 3, k8 = k & 7;
            const int tt = k8 & 3, half = k8 >> 2;
            const float v[4] = {b_st[j].x, b_st[j].y, b_st[j].z, b_st[j].w};
#pragma unroll
            for (int e = 0; e < 4; e++) {
                const int nloc = n4 * 4 + e;
                const int nf = nloc >> 3, gg = nloc & 7;
                Bs[buf * TFG_BS_BUF + (kc * 32 + nf) * 66 + (gg * 4 + tt) * 2 + half]
                    = f2tf32(v[e]);
            }
        }
    };
    auto compute = [&](int buf) {
#pragma unroll
        for (int kc = 0; kc < 2; kc++) {
            uint4 a[4];
            uint2 b[8];
#pragma unroll
            for (int mf = 0; mf < 4; mf++)
                a[mf] = *reinterpret_cast<const uint4*>(
                    As + buf * TFG_AS_BUF + (kc * 8 + wmg + mf) * 128 + lane * 4);
#pragma unroll
            for (int nf = 0; nf < 8; nf++)
                b[nf] = *reinterpret_cast<const uint2*>(
                    Bs + buf * TFG_BS_BUF + (kc * 32 + wng + nf) * 66 + lane * 2);
#pragma unroll
            for (int mf = 0; mf < 4; mf++)
#pragma unroll
                for (int nf = 0; nf < 8; nf++) {
                    asm volatile(
                        "mma.sync.aligned.m16n8k8.row.col.f32.tf32.tf32.f32 "
                        "{%0,%1,%2,%3}, {%4,%5,%6,%7}, {%8,%9}, {%0,%1,%2,%3};"
                        : "+f"(acc[mf][nf][0]), "+f"(acc[mf][nf][1]),
                          "+f"(acc[mf][nf][2]), "+f"(acc[mf][nf][3])
                        : "r"(a[mf].x), "r"(a[mf].y), "r"(a[mf].z), "r"(a[mf].w),
                          "r"(b[nf].x), "r"(b[nf].y));
                }
        }
    };

    ldgA(0); ldgB(0);
    stsA(0); stsB(0);
    __syncthreads();

    const int nk = (K + 15) >> 4;
    for (int i = 0; i < nk; i++) {
        const int buf = i & 1;
        if (i + 1 < nk) { ldgA((i + 1) * 16); ldgB((i + 1) * 16); }
        compute(buf);
        if (i + 1 < nk) {
            stsA(buf ^ 1); stsB(buf ^ 1);
            __syncthreads();
        }
    }

    // epilogue
#pragma unroll
    for (int nf = 0; nf < 8; nf++) {
        const int col = n0 + wn + nf * 8 + 2 * tig;
        const float b0 = bias[col];
        const float b1 = bias[col + 1];
#pragma unroll
        for (int mf = 0; mf < 4; mf++) {
            const int r0 = bm + wm + mf * 16 + g;
            const int r1 = r0 + 8;
            float v0 = acc[mf][nf][0] + b0;
            float v1 = acc[mf][nf][1] + b1;
            float v2 = acc[mf][nf][2] + b0;
            float v3 = acc[mf][nf][3] + b1;
            if (RELU) {
                v0 = fmaxf(v0, 0.f); v1 = fmaxf(v1, 0.f);
                v2 = fmaxf(v2, 0.f); v3 = fmaxf(v3, 0.f);
            }
            if (r0 < M) *reinterpret_cast<float2*>(C + (size_t)r0 * N + col) = make_float2(v0, v1);
            if (r1 < M) *reinterpret_cast<float2*>(C + (size_t)r1 * N + col) = make_float2(v2, v3);
        }
    }
}

// ===================== fp32 SIMT SGEMM (attn path only) ====================
template <bool RELU>
__global__ __launch_bounds__(256)
void sgemm_kernel(const float* __restrict__ A, const float* __restrict__ B,
                  const float* __restrict__ bias, float* __restrict__ C,
                  int M, int N, int K, int lda)
{
    __shared__ float As[8][128];
    __shared__ float Bs[8][128];

    const int tid = threadIdx.x;
    const int bm = blockIdx.y * 128;
    const int bn = blockIdx.x * 128;
    const int tx = tid & 15;
    const int ty = tid >> 4;

    const int arow = tid >> 1;
    const int acol = (tid & 1) * 4;
    const int brow = tid >> 5;
    const int bcol = (tid & 31) * 4;

    float acc[8][8];
#pragma unroll
    for (int i = 0; i < 8; i++)
#pragma unroll
        for (int j = 0; j < 8; j++) acc[i][j] = 0.f;

    for (int k0 = 0; k0 < K; k0 += 8) {
        {
            const int gr = bm + arow;
            float4 av = make_float4(0.f, 0.f, 0.f, 0.f);
            if (gr < M)
                av = *reinterpret_cast<const float4*>(A + (size_t)gr * lda + k0 + acol);
            As[acol + 0][arow] = av.x;
            As[acol + 1][arow] = av.y;
            As[acol + 2][arow] = av.z;
            As[acol + 3][arow] = av.w;
        }
        {
            const int gk = k0 + brow;
            float4 bv = make_float4(0.f, 0.f, 0.f, 0.f);
            if (gk < K)
                bv = *reinterpret_cast<const float4*>(B + (size_t)gk * N + bn + bcol);
            *reinterpret_cast<float4*>(&Bs[brow][bcol]) = bv;
        }
        __syncthreads();

#pragma unroll
        for (int k = 0; k < 8; k++) {
            float a[8], b[8];
            *reinterpret_cast<float4*>(a)     = *reinterpret_cast<const float4*>(&As[k][ty * 8]);
            *reinterpret_cast<float4*>(a + 4) = *reinterpret_cast<const float4*>(&As[k][ty * 8 + 4]);
            *reinterpret_cast<float4*>(b)     = *reinterpret_cast<const float4*>(&Bs[k][tx * 8]);
            *reinterpret_cast<float4*>(b + 4) = *reinterpret_cast<const float4*>(&Bs[k][tx * 8 + 4]);
#pragma unroll
            for (int i = 0; i < 8; i++)
#pragma unroll
                for (int j = 0; j < 8; j++)
                    acc[i][j] += a[i] * b[j];
        }
        __syncthreads();
    }

    const int ncol = bn + tx * 8;
    float bv[8];
#pragma unroll
    for (int j = 0; j < 8; j++) bv[j] = bias[ncol + j];

#pragma unroll
    for (int i = 0; i < 8; i++) {
        const int rr = bm + ty * 8 + i;
        if (rr < M) {
            float v[8];
#pragma unroll
            for (int j = 0; j < 8; j++) {
                float x = acc[i][j] + bv[j];
                if (RELU) x = fmaxf(x, 0.f);
                v[j] = x;
            }
            *reinterpret_cast<float4*>(C + (size_t)rr * N + ncol)     = *reinterpret_cast<float4*>(v);
            *reinterpret_cast<float4*>(C + (size_t)rr * N + ncol + 4) = *reinterpret_cast<float4*>(v + 4);
        }
    }
}

// ---------------- GEMV: y[m] = dot(X[m,:K], w) + b0 ----------------
__global__ void gemv_kernel(const float* __restrict__ X, const float* __restrict__ w,
                            const float* __restrict__ b, float* __restrict__ y,
                            int M, int K)
{
    const int row  = blockIdx.x * (blockDim.x >> 5) + (threadIdx.x >> 5);
    const int lane = threadIdx.x & 31;
    if (row >= M) return;
    const float4* x4 = reinterpret_cast<const float4*>(X + (size_t)row * K);
    const float4* w4 = reinterpret_cast<const float4*>(w);
    float acc = 0.f;
    const int K4 = K >> 2;
    for (int i = lane; i < K4; i += 32) {
        float4 a = x4[i], c = w4[i];
        acc += a.x * c.x + a.y * c.y + a.z * c.z + a.w * c.w;
    }
#pragma unroll
    for (int o = 16; o; o >>= 1) acc += __shfl_xor_sync(0xffffffffu, acc, o);
    if (lane == 0) y[row] = acc + b[0];
}

// ---------------- span featurization: builds g_i[N, 2580] ----------------
__global__ void span_kernel(const float* __restrict__ states, const float* __restrict__ embeds,
                            const float* __restrict__ wemb, const int* __restrict__ starts,
                            const int* __restrict__ widths, const float* __restrict__ attns,
                            float* __restrict__ gi, int N)
{
    const int warp = (blockIdx.x * blockDim.x + threadIdx.x) >> 5;
    const int lane = threadIdx.x & 31;
    if (warp >= N) return;

    const int s = starts[warp];
    const int w = widths[warp];

    float a = (lane < w) ? attns[s + lane] : -INFINITY;
    float m = a;
#pragma unroll
    for (int o = 16; o; o >>= 1) m = fmaxf(m, __shfl_xor_sync(0xffffffffu, m, o));
    float e = (lane < w) ? expf(a - m) : 0.f;
    float sum = e;
#pragma unroll
    for (int o = 16; o; o >>= 1) sum += __shfl_xor_sync(0xffffffffu, sum, o);
    const float wgt = e / sum;

    float* out = gi + (size_t)warp * GI_D;

    const float4* ss = reinterpret_cast<const float4*>(states + (size_t)s * STATE_D);
    const float4* se = reinterpret_cast<const float4*>(states + (size_t)(s + w - 1) * STATE_D);
    float4* o0 = reinterpret_cast<float4*>(out);
    float4* o1 = reinterpret_cast<float4*>(out + STATE_D);
#pragma unroll
    for (int i = lane; i < STATE_D / 4; i += 32) {
        o0[i] = ss[i];
        o1[i] = se[i];
    }

    float4* o2 = reinterpret_cast<float4*>(out + 2 * STATE_D);
#pragma unroll
    for (int i = lane; i < EMBED_D / 4; i += 32) {
        float4 acc = make_float4(0.f, 0.f, 0.f, 0.f);
        for (int j = 0; j < w; j++) {
            const float wj = __shfl_sync(0xffffffffu, wgt, j);
            const float4 ev = reinterpret_cast<const float4*>(embeds + (size_t)(s + j) * EMBED_D)[i];
            acc.x += wj * ev.x; acc.y += wj * ev.y;
            acc.z += wj * ev.z; acc.w += wj * ev.w;
        }
        o2[i] = acc;
    }

    const int bucket = (w >= 1) + (w >= 2) + (w >= 3) + (w >= 4) + (w >= 8);
    if (lane < DIST_D)
        out[2 * STATE_D + EMBED_D + lane] = wemb[bucket * DIST_D + lane];
}

// ---------------- launch ----------------
extern "C" void kernel_launch(void* const* d_in, const int* in_sizes, int n_in,
                              void* d_out, int out_size)
{
    const float* states = (const float*)d_in[0];
    const float* embeds = (const float*)d_in[1];
    const float* aW1 = (const float*)d_in[2];  const float* ab1 = (const float*)d_in[3];
    const float* aW2 = (const float*)d_in[4];  const float* ab2 = (const float*)d_in[5];
    const float* aW3 = (const float*)d_in[6];  const float* ab3 = (const float*)d_in[7];
    const float* sW1 = (const float*)d_in[8];  const float* sb1 = (const float*)d_in[9];
    const float* sW2 = (const float*)d_in[10]; const float* sb2 = (const float*)d_in[11];
    const float* sW3 = (const float*)d_in[12]; const float* sb3 = (const float*)d_in[13];
    const float* wemb = (const float*)d_in[14];
    const int* sstarts = (const int*)d_in[15];
    const int* swidths = (const int*)d_in[16];
    const int N = in_sizes[15];   // 40915 spans

    float* out    = (float*)d_out;
    float* gi     = out;                         // [N, 2580]
    float* scores = out + (size_t)N * GI_D;      // [N]

    float *h1, *h2, *attns, *s1, *s2;
    cudaGetSymbolAddress((void**)&h1,    g_h1);
    cudaGetSymbolAddress((void**)&h2,    g_h2);
    cudaGetSymbolAddress((void**)&attns, g_attns);
    cudaGetSymbolAddress((void**)&s1,    g_s1);
    cudaGetSymbolAddress((void**)&s2,    g_s2);

    cudaFuncSetAttribute(tf32_gemm_kernel<true>,
                         cudaFuncAttributeMaxDynamicSharedMemorySize, TFG_SMEM_BYTES);

    // 1) attention MLP over tokens (fp32 — feeds g_i, keep exact)
    {
        dim3 grid(HID / 128, T_TOK / 128);
        sgemm_kernel<true><<<grid, 256>>>(states, aW1, ab1, h1, T_TOK, HID, STATE_D, STATE_D);
        sgemm_kernel<true><<<grid, 256>>>(h1, aW2, ab2, h2, T_TOK, HID, HID, HID);
        gemv_kernel<<<(T_TOK * 32 + 255) / 256, 256>>>(h2, aW3, ab3, attns, T_TOK, HID);
    }

    // 2) span featurization -> g_i (directly into d_out)
    {
        const int warps_per_block = 8;
        const int blocks = (N + warps_per_block - 1) / warps_per_block;
        span_kernel<<<blocks, warps_per_block * 32>>>(states, embeds, wemb, sstarts, swidths,
                                                      attns, gi, N);
    }

    // 3) score MLP over spans (tf32 mma.sync, fragment-permuted SMEM)
    {
        dim3 grid(HID / 256, (N + 127) / 128);
        tf32_gemm_kernel<true><<<grid, 256, TFG_SMEM_BYTES>>>(gi, sW1, sb1, s1, N, HID, GI_D, GI_D);
        tf32_gemm_kernel<true><<<grid, 256, TFG_SMEM_BYTES>>>(s1, sW2, sb2, s2, N, HID, HID, HID);
        gemv_kernel<<<(N * 32 + 255) / 256, 256>>>(s2, sW3, sb3, scores, N, HID);
    }
}

// round 7
// speedup vs baseline: 6.5884x; 2.2266x over previous
#include <cuda_runtime.h>
#include <cuda_bf16.h>
#include <math.h>
#include <stdint.h>

// ---------------- problem constants ----------------
#define T_TOK   4096
#define STATE_D 1024
#define EMBED_D 512
#define DIST_D  20
#define HID     1024
#define GI_D    2580      // 2*STATE_D + EMBED_D + DIST_D
#define MAX_W   10
#define NBUCK   9

// ---------------- scratch (static device globals; no allocs) --------------
__device__ float g_h1[(size_t)T_TOK * HID];
__device__ float g_h2[(size_t)T_TOK * HID];
__device__ float g_attns[T_TOK];
__device__ float g_pa[(size_t)T_TOK * HID];
__device__ float g_pb[(size_t)T_TOK * HID];
__device__ float g_ec[(size_t)T_TOK * HID];
__device__ float g_wd[(size_t)NBUCK * HID];
__device__ float g_s1[(size_t)40960 * HID];
__device__ float g_s2[(size_t)40960 * HID];

__device__ __forceinline__ uint32_t f2tf32(float x) {
    uint32_t r;
    asm("cvt.rna.tf32.f32 %0, %1;" : "=r"(r) : "f"(x));
    return r;
}

// ============= tf32 mma.sync GEMM, fragment-permuted SMEM ==================
// C[M,N] = act(A[M,K] @ B[K,N] [+ bias]), N % 256 == 0.
// Block tile 128x256x16, 8 warps 2(m) x 4(n), warp tile 64x64, m16n8k8.
#define TFG_AS_BUF 2048            // u32 per A buffer
#define TFG_BS_BUF 4224            // u32 per B buffer (64 groups * 66)
#define TFG_SMEM_BYTES ((2 * TFG_AS_BUF + 2 * TFG_BS_BUF) * 4)   // 50176

template <bool RELU, bool BIAS>
__global__ __launch_bounds__(256, 1)
void tf32_gemm_kernel(const float* __restrict__ A, const float* __restrict__ B,
                      const float* __restrict__ bias, float* __restrict__ C,
                      int M, int N, int K, int lda)
{
    extern __shared__ uint32_t sh[];
    uint32_t* As = sh;
    uint32_t* Bs = sh + 2 * TFG_AS_BUF;

    const int tid  = threadIdx.x;
    const int warp = tid >> 5;
    const int lane = tid & 31;
    const int g    = lane >> 2;
    const int tig  = lane & 3;
    const int bm   = blockIdx.y * 128;
    const int n0   = blockIdx.x * 256;
    const int wm   = (warp & 1) * 64;
    const int wn   = (warp >> 1) * 64;
    const int wmg  = wm >> 4;
    const int wng  = wn >> 3;

    float acc[4][8][4];
#pragma unroll
    for (int mf = 0; mf < 4; mf++)
#pragma unroll
        for (int nf = 0; nf < 8; nf++)
#pragma unroll
            for (int q = 0; q < 4; q++) acc[mf][nf][q] = 0.f;

    float  a_st[2][4];
    float4 b_st[4];

    auto ldgA = [&](int k0) {
#pragma unroll
        for (int j = 0; j < 2; j++) {
            const int slot = tid + j * 256;
            const int grp  = slot >> 5;
            const int ln   = slot & 31;
            const int kc   = grp >> 3, fr = grp & 7;
            const int gg   = ln >> 2,  tt = ln & 3;
            const int r0   = bm + fr * 16 + gg;
            const int c0   = k0 + kc * 8 + tt;
            const float* base = A + (size_t)r0 * lda + c0;
            const bool rok0 = r0 < M, rok1 = (r0 + 8) < M;
            const bool cok0 = c0 < K, cok1 = (c0 + 4) < K;
            a_st[j][0] = (rok0 && cok0) ? base[0] : 0.f;
            a_st[j][1] = (rok1 && cok0) ? base[(size_t)8 * lda] : 0.f;
            a_st[j][2] = (rok0 && cok1) ? base[4] : 0.f;
            a_st[j][3] = (rok1 && cok1) ? base[(size_t)8 * lda + 4] : 0.f;
        }
    };
    auto stsA = [&](int buf) {
#pragma unroll
        for (int j = 0; j < 2; j++) {
            const int slot = tid + j * 256;
            uint4 u;
            u.x = f2tf32(a_st[j][0]); u.y = f2tf32(a_st[j][1]);
            u.z = f2tf32(a_st[j][2]); u.w = f2tf32(a_st[j][3]);
            *reinterpret_cast<uint4*>(As + buf * TFG_AS_BUF + slot * 4) = u;
        }
    };
    auto ldgB = [&](int k0) {
#pragma unroll
        for (int j = 0; j < 4; j++) {
            const int i  = tid + j * 256;
            const int k  = i >> 6;
            const int n4 = i & 63;
            const int gk = k0 + k;
            if (gk < K)
                b_st[j] = *reinterpret_cast<const float4*>(B + (size_t)gk * N + n0 + n4 * 4);
            else
                b_st[j] = make_float4(0.f, 0.f, 0.f, 0.f);
        }
    };
    auto stsB = [&](int buf) {
#pragma unroll
        for (int j = 0; j < 4; j++) {
            const int i  = tid + j * 256;
            const int k  = i >> 6, n4 = i & 63;
            const int kc = k >> 3, k8 = k & 7;
            const int tt = k8 & 3, half = k8 >> 2;
            const float v[4] = {b_st[j].x, b_st[j].y, b_st[j].z, b_st[j].w};
#pragma unroll
            for (int e = 0; e < 4; e++) {
                const int nloc = n4 * 4 + e;
                const int nf = nloc >> 3, gg = nloc & 7;
                Bs[buf * TFG_BS_BUF + (kc * 32 + nf) * 66 + (gg * 4 + tt) * 2 + half]
                    = f2tf32(v[e]);
            }
        }
    };
    auto compute = [&](int buf) {
#pragma unroll
        for (int kc = 0; kc < 2; kc++) {
            uint4 a[4];
            uint2 b[8];
#pragma unroll
            for (int mf = 0; mf < 4; mf++)
                a[mf] = *reinterpret_cast<const uint4*>(
                    As + buf * TFG_AS_BUF + (kc * 8 + wmg + mf) * 128 + lane * 4);
#pragma unroll
            for (int nf = 0; nf < 8; nf++)
                b[nf] = *reinterpret_cast<const uint2*>(
                    Bs + buf * TFG_BS_BUF + (kc * 32 + wng + nf) * 66 + lane * 2);
#pragma unroll
            for (int mf = 0; mf < 4; mf++)
#pragma unroll
                for (int nf = 0; nf < 8; nf++) {
                    asm volatile(
                        "mma.sync.aligned.m16n8k8.row.col.f32.tf32.tf32.f32 "
                        "{%0,%1,%2,%3}, {%4,%5,%6,%7}, {%8,%9}, {%0,%1,%2,%3};"
                        : "+f"(acc[mf][nf][0]), "+f"(acc[mf][nf][1]),
                          "+f"(acc[mf][nf][2]), "+f"(acc[mf][nf][3])
                        : "r"(a[mf].x), "r"(a[mf].y), "r"(a[mf].z), "r"(a[mf].w),
                          "r"(b[nf].x), "r"(b[nf].y));
                }
        }
    };

    ldgA(0); ldgB(0);
    stsA(0); stsB(0);
    __syncthreads();

    const int nk = (K + 15) >> 4;
    for (int i = 0; i < nk; i++) {
        const int buf = i & 1;
        if (i + 1 < nk) { ldgA((i + 1) * 16); ldgB((i + 1) * 16); }
        compute(buf);
        if (i + 1 < nk) {
            stsA(buf ^ 1); stsB(buf ^ 1);
            __syncthreads();
        }
    }

#pragma unroll
    for (int nf = 0; nf < 8; nf++) {
        const int col = n0 + wn + nf * 8 + 2 * tig;
        const float b0 = BIAS ? bias[col]     : 0.f;
        const float b1 = BIAS ? bias[col + 1] : 0.f;
#pragma unroll
        for (int mf = 0; mf < 4; mf++) {
            const int r0 = bm + wm + mf * 16 + g;
            const int r1 = r0 + 8;
            float v0 = acc[mf][nf][0] + b0;
            float v1 = acc[mf][nf][1] + b1;
            float v2 = acc[mf][nf][2] + b0;
            float v3 = acc[mf][nf][3] + b1;
            if (RELU) {
                v0 = fmaxf(v0, 0.f); v1 = fmaxf(v1, 0.f);
                v2 = fmaxf(v2, 0.f); v3 = fmaxf(v3, 0.f);
            }
            if (r0 < M) *reinterpret_cast<float2*>(C + (size_t)r0 * N + col) = make_float2(v0, v1);
            if (r1 < M) *reinterpret_cast<float2*>(C + (size_t)r1 * N + col) = make_float2(v2, v3);
        }
    }
}

// ---------------- GEMV: y[m] = dot(X[m,:K], w) + b0 ----------------
__global__ void gemv_kernel(const float* __restrict__ X, const float* __restrict__ w,
                            const float* __restrict__ b, float* __restrict__ y,
                            int M, int K)
{
    const int row  = blockIdx.x * (blockDim.x >> 5) + (threadIdx.x >> 5);
    const int lane = threadIdx.x & 31;
    if (row >= M) return;
    const float4* x4 = reinterpret_cast<const float4*>(X + (size_t)row * K);
    const float4* w4 = reinterpret_cast<const float4*>(w);
    float acc = 0.f;
    const int K4 = K >> 2;
    for (int i = lane; i < K4; i += 32) {
        float4 a = x4[i], c = w4[i];
        acc += a.x * c.x + a.y * c.y + a.z * c.z + a.w * c.w;
    }
#pragma unroll
    for (int o = 16; o; o >>= 1) acc += __shfl_xor_sync(0xffffffffu, acc, o);
    if (lane == 0) y[row] = acc + b[0];
}

// ------------- width-bucket layer-1 contribution: Wd[b] = wemb[b]@W1d + b1 --
__global__ void wd_kernel(const float* __restrict__ wemb, const float* __restrict__ W1d,
                          const float* __restrict__ b1, float* __restrict__ Wd)
{
    const int b = blockIdx.x;
    const int h = threadIdx.x;
    float acc = b1[h];
#pragma unroll
    for (int d = 0; d < DIST_D; d++)
        acc += wemb[b * DIST_D + d] * W1d[(size_t)d * HID + h];
    Wd[(size_t)b * HID + h] = acc;
}

// -------- fused span featurization + score-MLP layer 1 ---------------------
// one warp per span: writes g_i row AND s1 row = relu(Pa[s]+Pb[e]+Σw·Ec+Wd[b])
__global__ __launch_bounds__(256)
void span_fused_kernel(const float* __restrict__ states, const float* __restrict__ embeds,
                       const float* __restrict__ wemb, const int* __restrict__ starts,
                       const int* __restrict__ widths, const float* __restrict__ attns,
                       const float* __restrict__ Pa, const float* __restrict__ Pb,
                       const float* __restrict__ Ec, const float* __restrict__ Wd,
                       float* __restrict__ gi, float* __restrict__ s1, int N)
{
    const int warp = (blockIdx.x * blockDim.x + threadIdx.x) >> 5;
    const int lane = threadIdx.x & 31;
    if (warp >= N) return;

    const int s = starts[warp];
    const int w = widths[warp];
    const int e = s + w - 1;

    // --- softmax over valid slots ---
    float a = (lane < w) ? attns[s + lane] : -INFINITY;
    float m = a;
#pragma unroll
    for (int o = 16; o; o >>= 1) m = fmaxf(m, __shfl_xor_sync(0xffffffffu, m, o));
    float ex = (lane < w) ? expf(a - m) : 0.f;
    float sum = ex;
#pragma unroll
    for (int o = 16; o; o >>= 1) sum += __shfl_xor_sync(0xffffffffu, sum, o);
    const float wgt = ex / sum;

    float* out = gi + (size_t)warp * GI_D;

    // --- g_i: start / end state copies ---
    const float4* ss = reinterpret_cast<const float4*>(states + (size_t)s * STATE_D);
    const float4* se = reinterpret_cast<const float4*>(states + (size_t)e * STATE_D);
    float4* o0 = reinterpret_cast<float4*>(out);
    float4* o1 = reinterpret_cast<float4*>(out + STATE_D);
#pragma unroll
    for (int i = lane; i < STATE_D / 4; i += 32) {
        o0[i] = ss[i];
        o1[i] = se[i];
    }

    // --- g_i: attention-pooled embeds ---
    float4* o2 = reinterpret_cast<float4*>(out + 2 * STATE_D);
#pragma unroll
    for (int i = lane; i < EMBED_D / 4; i += 32) {
        float4 acc = make_float4(0.f, 0.f, 0.f, 0.f);
        for (int j = 0; j < w; j++) {
            const float wj = __shfl_sync(0xffffffffu, wgt, j);
            const float4 ev = reinterpret_cast<const float4*>(embeds + (size_t)(s + j) * EMBED_D)[i];
            acc.x += wj * ev.x; acc.y += wj * ev.y;
            acc.z += wj * ev.z; acc.w += wj * ev.w;
        }
        o2[i] = acc;
    }

    // --- g_i: width bucket embedding ---
    const int bucket = (w >= 1) + (w >= 2) + (w >= 3) + (w >= 4) + (w >= 8);
    if (lane < DIST_D)
        out[2 * STATE_D + EMBED_D + lane] = wemb[bucket * DIST_D + lane];

    // --- layer-1: h1 = relu(Pa[s] + Pb[e] + Σ wgt_j·Ec[s+j] + Wd[bucket]) ---
    const float4* pa = reinterpret_cast<const float4*>(Pa + (size_t)s * HID);
    const float4* pb = reinterpret_cast<const float4*>(Pb + (size_t)e * HID);
    const float4* wd = reinterpret_cast<const float4*>(Wd + (size_t)bucket * HID);
    float4 acc[8];
#pragma unroll
    for (int q = 0; q < 8; q++) {
        const int i = lane + q * 32;
        const float4 va = pa[i], vb = pb[i], vd = wd[i];
        acc[q].x = va.x + vb.x + vd.x;
        acc[q].y = va.y + vb.y + vd.y;
        acc[q].z = va.z + vb.z + vd.z;
        acc[q].w = va.w + vb.w + vd.w;
    }
    for (int j = 0; j < w; j++) {
        const float wj = __shfl_sync(0xffffffffu, wgt, j);
        const float4* ec = reinterpret_cast<const float4*>(Ec + (size_t)(s + j) * HID);
#pragma unroll
        for (int q = 0; q < 8; q++) {
            const float4 ev = ec[lane + q * 32];
            acc[q].x += wj * ev.x; acc[q].y += wj * ev.y;
            acc[q].z += wj * ev.z; acc[q].w += wj * ev.w;
        }
    }
    float4* s1r = reinterpret_cast<float4*>(s1 + (size_t)warp * HID);
#pragma unroll
    for (int q = 0; q < 8; q++) {
        float4 v = acc[q];
        v.x = fmaxf(v.x, 0.f); v.y = fmaxf(v.y, 0.f);
        v.z = fmaxf(v.z, 0.f); v.w = fmaxf(v.w, 0.f);
        s1r[lane + q * 32] = v;
    }
}

// ---------------- launch ----------------
extern "C" void kernel_launch(void* const* d_in, const int* in_sizes, int n_in,
                              void* d_out, int out_size)
{
    const float* states = (const float*)d_in[0];
    const float* embeds = (const float*)d_in[1];
    const float* aW1 = (const float*)d_in[2];  const float* ab1 = (const float*)d_in[3];
    const float* aW2 = (const float*)d_in[4];  const float* ab2 = (const float*)d_in[5];
    const float* aW3 = (const float*)d_in[6];  const float* ab3 = (const float*)d_in[7];
    const float* sW1 = (const float*)d_in[8];  const float* sb1 = (const float*)d_in[9];
    const float* sW2 = (const float*)d_in[10]; const float* sb2 = (const float*)d_in[11];
    const float* sW3 = (const float*)d_in[12]; const float* sb3 = (const float*)d_in[13];
    const float* wemb = (const float*)d_in[14];
    const int* sstarts = (const int*)d_in[15];
    const int* swidths = (const int*)d_in[16];
    const int N = in_sizes[15];   // 40915 spans

    float* out    = (float*)d_out;
    float* gi     = out;                         // [N, 2580]
    float* scores = out + (size_t)N * GI_D;      // [N]

    float *h1, *h2, *attns, *pa, *pb, *ec, *wd, *s1, *s2;
    cudaGetSymbolAddress((void**)&h1,    g_h1);
    cudaGetSymbolAddress((void**)&h2,    g_h2);
    cudaGetSymbolAddress((void**)&attns, g_attns);
    cudaGetSymbolAddress((void**)&pa,    g_pa);
    cudaGetSymbolAddress((void**)&pb,    g_pb);
    cudaGetSymbolAddress((void**)&ec,    g_ec);
    cudaGetSymbolAddress((void**)&wd,    g_wd);
    cudaGetSymbolAddress((void**)&s1,    g_s1);
    cudaGetSymbolAddress((void**)&s2,    g_s2);

    cudaFuncSetAttribute(tf32_gemm_kernel<true, true>,
                         cudaFuncAttributeMaxDynamicSharedMemorySize, TFG_SMEM_BYTES);
    cudaFuncSetAttribute(tf32_gemm_kernel<false, false>,
                         cudaFuncAttributeMaxDynamicSharedMemorySize, TFG_SMEM_BYTES);

    // 1) attention MLP over tokens (tf32 — feeds only softmax weights)
    {
        dim3 grid(HID / 256, T_TOK / 128);
        tf32_gemm_kernel<true, true><<<grid, 256, TFG_SMEM_BYTES>>>(
            states, aW1, ab1, h1, T_TOK, HID, STATE_D, STATE_D);
        tf32_gemm_kernel<true, true><<<grid, 256, TFG_SMEM_BYTES>>>(
            h1, aW2, ab2, h2, T_TOK, HID, HID, HID);
        gemv_kernel<<<(T_TOK * 32 + 255) / 256, 256>>>(h2, aW3, ab3, attns, T_TOK, HID);
    }

    // 2) token-level layer-1 precomputation: Pa, Pb, Ec (no bias, no relu)
    {
        dim3 grid(HID / 256, T_TOK / 128);
        tf32_gemm_kernel<false, false><<<grid, 256, TFG_SMEM_BYTES>>>(
            states, sW1, nullptr, pa, T_TOK, HID, STATE_D, STATE_D);
        tf32_gemm_kernel<false, false><<<grid, 256, TFG_SMEM_BYTES>>>(
            states, sW1 + (size_t)STATE_D * HID, nullptr, pb, T_TOK, HID, STATE_D, STATE_D);
        tf32_gemm_kernel<false, false><<<grid, 256, TFG_SMEM_BYTES>>>(
            embeds, sW1 + (size_t)2 * STATE_D * HID, nullptr, ec, T_TOK, HID, EMBED_D, EMBED_D);
        wd_kernel<<<NBUCK, HID>>>(wemb, sW1 + (size_t)GI_D * HID - (size_t)DIST_D * HID, sb1, wd);
    }

    // 3) fused span featurization + layer 1 -> g_i (d_out) and s1
    {
        const int warps_per_block = 8;
        const int blocks = (N + warps_per_block - 1) / warps_per_block;
        span_fused_kernel<<<blocks, warps_per_block * 32>>>(
            states, embeds, wemb, sstarts, swidths, attns, pa, pb, ec, wd, gi, s1, N);
    }

    // 4) layer 2 (tf32) + final gemv
    {
        dim3 grid(HID / 256, (N + 127) / 128);
        tf32_gemm_kernel<true, true><<<grid, 256, TFG_SMEM_BYTES>>>(
            s1, sW2, sb2, s2, N, HID, HID, HID);
        gemv_kernel<<<(N * 32 + 255) / 256, 256>>>(s2, sW3, sb3, scores, N, HID);
    }
}